// round 3
// baseline (speedup 1.0000x reference)
#include <cuda_runtime.h>
#include <cstdint>

// Problem dims
#define BB 256
#define NN 768
#define HH 3072
#define LL 19

// Fixed CSR/CSC capacities (construction guarantees: W_vn<=3, masks<=7, W_out<=4, bm/S/cm cols = 1)
#define CAP_W 4
#define CAP_M 8
#define CAP_O 4
#define CAP_B 2
#define CAP_S 2
#define CAP_C 2

// ---------------- device scratch (no allocation allowed) ----------------
__device__ __align__(16) uint16_t g_w_idx [LL * HH * CAP_W];
__device__ __align__(16) float    g_w_val [LL * HH * CAP_W];
__device__ __align__(16) uint16_t g_mf_idx[HH * CAP_M];
__device__ __align__(16) uint16_t g_mc_idx[HH * CAP_M];
__device__ __align__(16) uint16_t g_wo_idx[NN * CAP_O];
__device__ __align__(16) float    g_wo_val[NN * CAP_O];
__device__ __align__(16) uint16_t g_bm_idx[HH * CAP_B];
__device__ __align__(16) float    g_bm_val[HH * CAP_B];
__device__ __align__(16) uint16_t g_s_idx [20 * NN * CAP_S];
__device__ __align__(16) float    g_s_val [20 * NN * CAP_S];
__device__ __align__(16) uint16_t g_cm_idx[NN * CAP_C];
__device__ __align__(16) float    g_cm_val[NN * CAP_C];

// ---------------- sparsity extraction ----------------
// Warp-per-row scan (row-major, coalesced float4 loads). Deterministic in-order
// compaction via warp prefix sum. Pads unused slots with (sentinel, 0).
__device__ __forceinline__ void row_scan(const float* __restrict__ M, int R, int C, int CAP,
                                         uint16_t* __restrict__ idx, float* __restrict__ val,
                                         bool isMask, int sentinel)
{
    int row  = (blockIdx.x * blockDim.x + threadIdx.x) >> 5;
    int lane = threadIdx.x & 31;
    if (row >= R) return;
    const float4* rp = reinterpret_cast<const float4*>(M + (size_t)row * C);
    int nC4 = C >> 2;          // 768 or 192: divisible by 32 -> uniform warp loops
    int base = 0;
    for (int c = lane; c < nC4; c += 32) {
        float4 v = rp[c];
        int m0 = (v.x != 0.0f), m1 = (v.y != 0.0f), m2 = (v.z != 0.0f), m3 = (v.w != 0.0f);
        int cnt = m0 + m1 + m2 + m3;
        int sc = cnt;
        #pragma unroll
        for (int d = 1; d < 32; d <<= 1) {
            int o = __shfl_up_sync(0xffffffffu, sc, d);
            if (lane >= d) sc += o;
        }
        int pos = base + sc - cnt;   // exclusive prefix
        int col = c << 2;
        if (m0) { if (pos < CAP) { idx[row*CAP+pos] = (uint16_t)(col    ); if (!isMask) val[row*CAP+pos] = v.x; } pos++; }
        if (m1) { if (pos < CAP) { idx[row*CAP+pos] = (uint16_t)(col + 1); if (!isMask) val[row*CAP+pos] = v.y; } pos++; }
        if (m2) { if (pos < CAP) { idx[row*CAP+pos] = (uint16_t)(col + 2); if (!isMask) val[row*CAP+pos] = v.z; } pos++; }
        if (m3) { if (pos < CAP) { idx[row*CAP+pos] = (uint16_t)(col + 3); if (!isMask) val[row*CAP+pos] = v.w; } pos++; }
        base += __shfl_sync(0xffffffffu, sc, 31);
    }
    if (base > CAP) base = CAP;
    for (int p = base + lane; p < CAP; p += 32) {
        idx[row*CAP+p] = (uint16_t)sentinel;
        if (!isMask) val[row*CAP+p] = 0.0f;
    }
}

// Thread-per-column scan (reads are coalesced across the warp each row step).
// Deterministic sequential order within a column. Pads with (0, 0).
__device__ __forceinline__ void col_scan(const float* __restrict__ M, int R, int C, int CAP,
                                         uint16_t* __restrict__ idx, float* __restrict__ val)
{
    int col = blockIdx.x * blockDim.x + threadIdx.x;
    int sl  = blockIdx.y;
    if (col >= C) return;
    const float* p = M + (size_t)sl * R * C;
    uint16_t* oi = idx + ((size_t)sl * C + col) * CAP;
    float*    ov = val + ((size_t)sl * C + col) * CAP;
    int cnt = 0;
    #pragma unroll 8
    for (int r = 0; r < R; r++) {
        float v = p[(size_t)r * C + col];
        if (v != 0.0f && cnt < CAP) { oi[cnt] = (uint16_t)r; ov[cnt] = v; cnt++; }
    }
    for (; cnt < CAP; cnt++) { oi[cnt] = 0; ov[cnt] = 0.0f; }
}

__global__ void k_wvn (const float* __restrict__ M){ row_scan(M, LL*HH, HH, CAP_W, g_w_idx,  g_w_val,  false, 0); }
__global__ void k_wout(const float* __restrict__ M){ row_scan(M, NN,    HH, CAP_O, g_wo_idx, g_wo_val, false, 0); }
__global__ void k_mf  (const float* __restrict__ M){ row_scan(M, HH,    NN, CAP_M, g_mf_idx, nullptr,  true,  NN); }
__global__ void k_mc  (const float* __restrict__ M){ row_scan(M, HH,    HH, CAP_M, g_mc_idx, nullptr,  true,  HH); }
__global__ void k_bm  (const float* __restrict__ M){ col_scan(M, NN,    HH, CAP_B, g_bm_idx, g_bm_val); }
__global__ void k_s   (const float* __restrict__ M){ col_scan(M, NN,    NN, CAP_S, g_s_idx,  g_s_val);  }
__global__ void k_cm  (const float* __restrict__ M){ col_scan(M, NN,    NN, CAP_C, g_cm_idx, g_cm_val); }

// ---------------- math helpers (fast MUFU intrinsics, ~1e-7 rel err) ----------------
__device__ __forceinline__ float fast_tanh_half(float z)   // tanh(z/2)
{
    float e = __expf(-fabsf(z));                       // e^{-|z|}, no overflow
    float r = __fdividef(1.0f - e, 1.0f + e);          // tanh(|z|/2)
    return copysignf(r, z);
}
__device__ __forceinline__ float two_atanh_clip(float t)   // 2*atanh(clip(t))
{
    t = fminf(fmaxf(t, -0.999999f), 0.999999f);
    return __logf(__fdividef(1.0f + t, 1.0f - t));
}
// Product of the nonzero gathered entries; 0 if all are zero.
// Sentinel-padded indices point at a guaranteed-0 slot, so they are skipped
// exactly like real zeros (matches reference semantics).
__device__ __forceinline__ float cn_prod8(uint4 q, const float* __restrict__ buf)
{
    int i0 = q.x & 0xffff, i1 = q.x >> 16;
    int i2 = q.y & 0xffff, i3 = q.y >> 16;
    int i4 = q.z & 0xffff, i5 = q.z >> 16;
    int i6 = q.w & 0xffff, i7 = q.w >> 16;
    float p = 1.0f; int any = 0; float v; bool nz;
    v = buf[i0]; nz = (v != 0.0f); any |= nz; p *= nz ? v : 1.0f;
    v = buf[i1]; nz = (v != 0.0f); any |= nz; p *= nz ? v : 1.0f;
    v = buf[i2]; nz = (v != 0.0f); any |= nz; p *= nz ? v : 1.0f;
    v = buf[i3]; nz = (v != 0.0f); any |= nz; p *= nz ? v : 1.0f;
    v = buf[i4]; nz = (v != 0.0f); any |= nz; p *= nz ? v : 1.0f;
    v = buf[i5]; nz = (v != 0.0f); any |= nz; p *= nz ? v : 1.0f;
    v = buf[i6]; nz = (v != 0.0f); any |= nz; p *= nz ? v : 1.0f;
    v = buf[i7]; nz = (v != 0.0f); any |= nz; p *= nz ? v : 1.0f;
    return any ? p : 0.0f;
}

// ---------------- the whole network, fused: one block per batch element ----------------
__global__ void __launch_bounds__(256, 2) bp_main(const float* __restrict__ x,
                                                  float* __restrict__ out)
{
    __shared__ float bufA[HH + 4], bufB[HH + 4], xrow[NN], ybuf[NN + 4];
    const int t = threadIdx.x;
    const int b = blockIdx.x;

    if (t == 0) { bufA[HH] = 0.0f; bufB[HH] = 0.0f; ybuf[NN] = 0.0f; }  // sentinel slots
    for (int n = t; n < NN; n += 256) xrow[n] = x[(size_t)b * NN + n];
    __syncthreads();

    // stage 0: t = tanh(0.5 x) (into ybuf), then h = CN(M_first, t)
    for (int n = t; n < NN; n += 256) ybuf[n] = fast_tanh_half(xrow[n]);
    __syncthreads();
    {
        const uint4* mf = reinterpret_cast<const uint4*>(g_mf_idx);
        for (int i = t; i < HH; i += 256) bufA[i] = cn_prod8(mf[i], ybuf);
    }
    __syncthreads();

    float* hb = bufA;
    float* ub = bufB;
    const uint4*    mc4 = reinterpret_cast<const uint4*>(g_mc_idx);
    const uint2*    wi2 = reinterpret_cast<const uint2*>(g_w_idx);
    const float4*   wv4 = reinterpret_cast<const float4*>(g_w_val);
    const uint32_t* bmi = reinterpret_cast<const uint32_t*>(g_bm_idx);
    const float2*   bmv = reinterpret_cast<const float2*>(g_bm_val);
    const uint32_t* si  = reinterpret_cast<const uint32_t*>(g_s_idx);
    const float2*   sv  = reinterpret_cast<const float2*>(g_s_val);

    for (int l = 0; l < LL; l++) {
        // u = 2*atanh(clip(h));  y = x @ S[l]  (sparse columns)
        for (int j = t; j < HH; j += 256) ub[j] = two_atanh_clip(hb[j]);
        for (int m = t; m < NN; m += 256) {
            uint32_t q = si[l * NN + m]; float2 w = sv[l * NN + m];
            ybuf[m] = w.x * xrow[q & 0xffff] + w.y * xrow[q >> 16];
        }
        __syncthreads();
        // v = tanh(0.5*(W u + bias_gather(y)))   (W rows: <=3 nnz; bias col: 1 nnz)
        for (int i = t; i < HH; i += 256) {
            uint32_t bq = bmi[i]; float2 bw = bmv[i];
            float z = bw.x * ybuf[bq & 0xffff] + bw.y * ybuf[bq >> 16];
            uint2 wq = wi2[l * HH + i]; float4 ww = wv4[l * HH + i];
            z += ww.x * ub[wq.x & 0xffff];
            z += ww.y * ub[wq.x >> 16];
            z += ww.z * ub[wq.y & 0xffff];
            z += ww.w * ub[wq.y >> 16];
            hb[i] = fast_tanh_half(z);
        }
        __syncthreads();
        // h' = CN(M_cn, v)
        for (int i = t; i < HH; i += 256) ub[i] = cn_prod8(mc4[i], hb);
        __syncthreads();
        float* tmp = hb; hb = ub; ub = tmp;
    }

    // output layer
    for (int j = t; j < HH; j += 256) ub[j] = two_atanh_clip(hb[j]);
    for (int m = t; m < NN; m += 256) {
        uint32_t q = si[19 * NN + m]; float2 w = sv[19 * NN + m];
        ybuf[m] = w.x * xrow[q & 0xffff] + w.y * xrow[q >> 16];
    }
    __syncthreads();
    {
        const uint2*    oi2 = reinterpret_cast<const uint2*>(g_wo_idx);
        const float4*   ov4 = reinterpret_cast<const float4*>(g_wo_val);
        const uint32_t* cmi = reinterpret_cast<const uint32_t*>(g_cm_idx);
        const float2*   cmv = reinterpret_cast<const float2*>(g_cm_val);
        for (int n = t; n < NN; n += 256) {
            uint32_t cq = cmi[n]; float2 cw = cmv[n];
            float s = cw.x * ybuf[cq & 0xffff] + cw.y * ybuf[cq >> 16];
            uint2 wq = oi2[n]; float4 ww = ov4[n];
            s += ww.x * ub[wq.x & 0xffff];
            s += ww.y * ub[wq.x >> 16];
            s += ww.z * ub[wq.y & 0xffff];
            s += ww.w * ub[wq.y >> 16];
            out[(size_t)b * NN + n] = __fdividef(1.0f, 1.0f + __expf(-s));
        }
    }
}

// ---------------- launch ----------------
extern "C" void kernel_launch(void* const* d_in, const int* in_sizes, int n_in,
                              void* d_out, int out_size)
{
    (void)in_sizes; (void)n_in; (void)out_size;
    const float* x    = (const float*)d_in[0];   // [256, 768]
    const float* Wvn  = (const float*)d_in[1];   // [19, 3072, 3072]
    const float* Wout = (const float*)d_in[2];   // [768, 3072]
    const float* S    = (const float*)d_in[3];   // [20, 768, 768]
    const float* bm   = (const float*)d_in[4];   // [768, 3072]
    const float* cm   = (const float*)d_in[5];   // [768, 768]
    const float* Mf   = (const float*)d_in[6];   // [3072, 768]
    const float* Mc   = (const float*)d_in[7];   // [3072, 3072]
    float* out = (float*)d_out;                  // [256, 768]

    // Sparsity extraction (8 warps/block -> 8 rows/block for row scans)
    k_wvn <<<(LL * HH + 7) / 8, 256>>>(Wvn);
    k_wout<<<(NN + 7) / 8,      256>>>(Wout);
    k_mf  <<<(HH + 7) / 8,      256>>>(Mf);
    k_mc  <<<(HH + 7) / 8,      256>>>(Mc);
    k_bm  <<<dim3((HH + 255) / 256, 1),  256>>>(bm);
    k_s   <<<dim3((NN + 255) / 256, 20), 256>>>(S);
    k_cm  <<<dim3((NN + 255) / 256, 1),  256>>>(cm);

    // Fused BP network: one block per batch element
    bp_main<<<BB, 256>>>(x, out);
}